// round 1
// baseline (speedup 1.0000x reference)
#include <cuda_runtime.h>
#include <math.h>

#define NDIM 256
#define IMG (NDIM * NDIM)
#define NIMG (128 * 3)

// Scratch (device globals: allocation inside kernel_launch is forbidden)
__device__ float g_C[NDIM * NDIM];
__device__ float g_t1[NIMG * IMG];
__device__ float g_t2[NIMG * IMG];

// Orthonormal DCT-II matrix: C[k,n] = cos(pi*(n+0.5)*k/N) * scale(k)
__global__ void init_C_kernel() {
    int idx = blockIdx.x * blockDim.x + threadIdx.x;
    if (idx >= NDIM * NDIM) return;
    int k = idx / NDIM;
    int n = idx % NDIM;
    double v = cos(M_PI * ((double)n + 0.5) * (double)k / (double)NDIM);
    double s = (k == 0) ? sqrt(1.0 / NDIM) : sqrt(2.0 / NDIM);
    g_C[idx] = (float)(v * s);
}

// Batched 256x256x256 SGEMM, Out[i,j] = sum_k A(i,k)*B(k,j) per image.
// MODE 0: T1 = C       * X      (in: gin,  out: g_t1)
// MODE 1: Y  = T1      * C^T    (in: g_t1, out: g_t2)  + per-batch mask epilogue
// MODE 2: T2 = C^T     * Y      (in: g_t2, out: g_t1)
// MODE 3: out= T2      * C      (in: g_t1, out: gout)
template <int MODE>
__global__ void __launch_bounds__(256) dct_gemm(const float* __restrict__ gin,
                                                float* __restrict__ gout,
                                                const float* __restrict__ tarr) {
    constexpr int BK = 16;
    __shared__ __align__(16) float As[BK][68];  // As[k][m]
    __shared__ __align__(16) float Bs[BK][68];  // Bs[k][j]

    const int img = blockIdx.z;
    const int m0 = blockIdx.y * 64;
    const int n0 = blockIdx.x * 64;
    const int tx = threadIdx.x;   // 0..15
    const int ty = threadIdx.y;   // 0..15
    const int tid = ty * 16 + tx;

    const float* inImg;
    if constexpr (MODE == 0)      inImg = gin  + (size_t)img * IMG;
    else if constexpr (MODE == 1) inImg = g_t1 + (size_t)img * IMG;
    else if constexpr (MODE == 2) inImg = g_t2 + (size_t)img * IMG;
    else                          inImg = g_t1 + (size_t)img * IMG;

    float acc[4][4];
#pragma unroll
    for (int i = 0; i < 4; i++)
#pragma unroll
        for (int j = 0; j < 4; j++) acc[i][j] = 0.0f;

    for (int k0 = 0; k0 < NDIM; k0 += BK) {
        // ---- load A tile into As[k][m] ----
#pragma unroll
        for (int u = 0; u < 4; u++) {
            int e = tid + 256 * u;
            if constexpr (MODE == 2) {
                // A(i,k) = C[k, i]  -> contiguous along m: coalesced
                int m = e & 63, k = e >> 6;
                As[k][m] = g_C[(k0 + k) * NDIM + (m0 + m)];
            } else if constexpr (MODE == 0) {
                int k = e & 15, m = e >> 4;
                As[k][m] = g_C[(m0 + m) * NDIM + (k0 + k)];
            } else {
                int k = e & 15, m = e >> 4;
                As[k][m] = inImg[(m0 + m) * NDIM + (k0 + k)];
            }
        }
        // ---- load B tile into Bs[k][j] ----
#pragma unroll
        for (int u = 0; u < 4; u++) {
            int e = tid + 256 * u;
            if constexpr (MODE == 1) {
                // B(k,j) = C[j, k] -> contiguous along k
                int k = e & 15, j = e >> 4;
                Bs[k][j] = g_C[(n0 + j) * NDIM + (k0 + k)];
            } else if constexpr (MODE == 3) {
                int j = e & 63, k = e >> 6;
                Bs[k][j] = g_C[(k0 + k) * NDIM + (n0 + j)];
            } else {
                int j = e & 63, k = e >> 6;
                Bs[k][j] = inImg[(k0 + k) * NDIM + (n0 + j)];
            }
        }
        __syncthreads();

#pragma unroll
        for (int k = 0; k < BK; k++) {
            float4 a4 = *reinterpret_cast<const float4*>(&As[k][ty * 4]);
            float4 b4 = *reinterpret_cast<const float4*>(&Bs[k][tx * 4]);
            float a[4] = {a4.x, a4.y, a4.z, a4.w};
            float b[4] = {b4.x, b4.y, b4.z, b4.w};
#pragma unroll
            for (int i = 0; i < 4; i++)
#pragma unroll
                for (int j = 0; j < 4; j++)
                    acc[i][j] = fmaf(a[i], b[j], acc[i][j]);
        }
        __syncthreads();
    }

    float* outImg;
    if constexpr (MODE == 3)      outImg = gout + (size_t)img * IMG;
    else if constexpr (MODE == 0) outImg = g_t1 + (size_t)img * IMG;
    else if constexpr (MODE == 1) outImg = g_t2 + (size_t)img * IMG;
    else                          outImg = g_t1 + (size_t)img * IMG;

    if constexpr (MODE == 1) {
        // mask: fade = exp(-(fk^2+fn^2)*tau), <0.01 -> 0, then *0.999 + 0.001
        const float PI_N = 0.01227184630308513f;  // pi/256
        float tb = tarr[img / 3];
        // sigma = exp(log(0.5)*(1-t) + log(20)*t) = exp(-log2e... ) -> affine in t
        float sig = expf(fmaf(tb, 3.6888794541139363f, -0.6931471805599453f));
        float tau = 0.5f * sig * sig;
#pragma unroll
        for (int i = 0; i < 4; i++) {
            int kk = m0 + ty * 4 + i;
            float fk = (float)kk * PI_N;
            float fk2 = fk * fk;
            float4 o;
            float* po = reinterpret_cast<float*>(&o);
#pragma unroll
            for (int j = 0; j < 4; j++) {
                int nn = n0 + tx * 4 + j;
                float fn = (float)nn * PI_N;
                float fade = expf(-(fk2 + fn * fn) * tau);
                if (fade < 0.01f) fade = 0.0f;
                po[j] = acc[i][j] * fmaf(fade, 0.999f, 0.001f);
            }
            *reinterpret_cast<float4*>(&outImg[kk * NDIM + n0 + tx * 4]) = o;
        }
    } else {
#pragma unroll
        for (int i = 0; i < 4; i++) {
            int row = m0 + ty * 4 + i;
            float4 o = make_float4(acc[i][0], acc[i][1], acc[i][2], acc[i][3]);
            *reinterpret_cast<float4*>(&outImg[row * NDIM + n0 + tx * 4]) = o;
        }
    }
}

extern "C" void kernel_launch(void* const* d_in, const int* in_sizes, int n_in,
                              void* d_out, int out_size) {
    const float* x = (const float*)d_in[0];   // (128,3,256,256) fp32
    const float* t = (const float*)d_in[1];   // (128,) fp32
    float* out = (float*)d_out;               // (128,3,256,256) fp32

    init_C_kernel<<<(NDIM * NDIM + 255) / 256, 256>>>();

    dim3 blk(16, 16, 1);
    dim3 grd(4, 4, NIMG);
    dct_gemm<0><<<grd, blk>>>(x, nullptr, t);
    dct_gemm<1><<<grd, blk>>>(nullptr, nullptr, t);
    dct_gemm<2><<<grd, blk>>>(nullptr, nullptr, t);
    dct_gemm<3><<<grd, blk>>>(nullptr, out, t);
}

// round 3
// speedup vs baseline: 1.2655x; 1.2655x over previous
#include <cuda_runtime.h>
#include <math.h>

#define NDIM 256
#define IMG (NDIM * NDIM)
#define NIMG (128 * 3)
#define BK 16
#define SST 136  // smem row stride (floats): 128 + 8, conflict-free for both loaders

// Scratch (device globals: allocation inside kernel_launch is forbidden)
__device__ float g_C[NDIM * NDIM];
__device__ float g_t1[NIMG * IMG];
__device__ float g_t2[NIMG * IMG];

// Orthonormal DCT-II matrix: C[k,n] = cos(pi*(n+0.5)*k/N) * scale(k)
__global__ void init_C_kernel() {
    int idx = blockIdx.x * blockDim.x + threadIdx.x;
    if (idx >= NDIM * NDIM) return;
    int k = idx / NDIM;
    int n = idx % NDIM;
    double v = cos(M_PI * ((double)n + 0.5) * (double)k / (double)NDIM);
    double s = (k == 0) ? sqrt(1.0 / NDIM) : sqrt(2.0 / NDIM);
    g_C[idx] = (float)(v * s);
}

// Tile loaders: fill S[k][r], k in [0,BK), r in [0,128).
// K-contig: elem(r,k) = base[(r0+r)*256 + k0 + k]  (k is the fast axis in gmem)
__device__ __forceinline__ void load_kcontig(float (*S)[SST], const float* __restrict__ base,
                                             int r0, int k0, int tid) {
#pragma unroll
    for (int u = 0; u < 2; u++) {
        int idx = tid * 2 + u;
        int r = idx >> 2;
        int kq = (idx & 3) * 4;
        float4 v = *reinterpret_cast<const float4*>(base + (size_t)(r0 + r) * NDIM + k0 + kq);
        S[kq + 0][r] = v.x;
        S[kq + 1][r] = v.y;
        S[kq + 2][r] = v.z;
        S[kq + 3][r] = v.w;
    }
}

// M-contig: elem(r,k) = base[(k0+k)*256 + r0 + r]  (r is the fast axis in gmem)
__device__ __forceinline__ void load_mcontig(float (*S)[SST], const float* __restrict__ base,
                                             int r0, int k0, int tid) {
    int k = tid >> 4;            // 0..15
    int mb = (tid & 15) * 4;     // 0..60
    const float* p = base + (size_t)(k0 + k) * NDIM + r0 + mb;
    float4 v0 = *reinterpret_cast<const float4*>(p);
    float4 v1 = *reinterpret_cast<const float4*>(p + 64);
    *reinterpret_cast<float4*>(&S[k][mb]) = v0;
    *reinterpret_cast<float4*>(&S[k][mb + 64]) = v1;
}

// Batched 256x256x256 SGEMM, Out[i,j] = sum_k A(i,k)*B(k,j) per image.
// MODE 0: T1 = C    * X     A: C   k-contig   B: X    m-contig
// MODE 1: Y  = T1   * C^T   A: T1  k-contig   B: C    k-contig   (+ mask epilogue)
// MODE 2: T2 = C^T  * Y     A: C   m-contig   B: t2   m-contig
// MODE 3: out= T2   * C     A: t1  k-contig   B: C    m-contig
template <int MODE>
__global__ void __launch_bounds__(256, 2) dct_gemm(const float* __restrict__ gin,
                                                   float* __restrict__ gout,
                                                   const float* __restrict__ tarr) {
    __shared__ __align__(16) float As[BK][SST];
    __shared__ __align__(16) float Bs[BK][SST];

    const int img = blockIdx.z;
    const int m0 = blockIdx.y * 128;
    const int n0 = blockIdx.x * 128;
    const int tid = threadIdx.x;
    const int tx = tid & 15;
    const int ty = tid >> 4;

    const float* inImg;
    if constexpr (MODE == 0)      inImg = gin  + (size_t)img * IMG;
    else if constexpr (MODE == 1) inImg = g_t1 + (size_t)img * IMG;
    else if constexpr (MODE == 2) inImg = g_t2 + (size_t)img * IMG;
    else                          inImg = g_t1 + (size_t)img * IMG;

    float acc[8][8];
#pragma unroll
    for (int i = 0; i < 8; i++)
#pragma unroll
        for (int j = 0; j < 8; j++) acc[i][j] = 0.0f;

    for (int k0 = 0; k0 < NDIM; k0 += BK) {
        if constexpr (MODE == 0) {
            load_kcontig(As, g_C, m0, k0, tid);
            load_mcontig(Bs, inImg, n0, k0, tid);
        } else if constexpr (MODE == 1) {
            load_kcontig(As, inImg, m0, k0, tid);
            load_kcontig(Bs, g_C, n0, k0, tid);
        } else if constexpr (MODE == 2) {
            load_mcontig(As, g_C, m0, k0, tid);
            load_mcontig(Bs, inImg, n0, k0, tid);
        } else {
            load_kcontig(As, inImg, m0, k0, tid);
            load_mcontig(Bs, g_C, n0, k0, tid);
        }
        __syncthreads();

#pragma unroll
        for (int k = 0; k < BK; k++) {
            float4 a0 = *reinterpret_cast<const float4*>(&As[k][ty * 4]);
            float4 a1 = *reinterpret_cast<const float4*>(&As[k][64 + ty * 4]);
            float4 b0 = *reinterpret_cast<const float4*>(&Bs[k][tx * 4]);
            float4 b1 = *reinterpret_cast<const float4*>(&Bs[k][64 + tx * 4]);
            float a[8] = {a0.x, a0.y, a0.z, a0.w, a1.x, a1.y, a1.z, a1.w};
            float b[8] = {b0.x, b0.y, b0.z, b0.w, b1.x, b1.y, b1.z, b1.w};
#pragma unroll
            for (int i = 0; i < 8; i++)
#pragma unroll
                for (int j = 0; j < 8; j++)
                    acc[i][j] = fmaf(a[i], b[j], acc[i][j]);
        }
        __syncthreads();
    }

    float* outImg;
    if constexpr (MODE == 3)      outImg = gout + (size_t)img * IMG;
    else if constexpr (MODE == 0) outImg = g_t1 + (size_t)img * IMG;
    else if constexpr (MODE == 1) outImg = g_t2 + (size_t)img * IMG;
    else                          outImg = g_t1 + (size_t)img * IMG;

    // Row/col global indices for the 8x8 microtile (halves at +0 and +64)
    int rowIdx[8], colIdx[8];
#pragma unroll
    for (int h = 0; h < 2; h++)
#pragma unroll
        for (int q = 0; q < 4; q++) {
            rowIdx[h * 4 + q] = m0 + h * 64 + ty * 4 + q;
            colIdx[h * 4 + q] = n0 + h * 64 + tx * 4 + q;
        }

    if constexpr (MODE == 1) {
        // mask: fade = exp(-(fk^2+fn^2)*tau) (separable), <0.01 -> 0, *0.999 + 0.001
        const float PI_N = 0.01227184630308513f;  // pi/256
        float tb = tarr[img / 3];
        float sig = expf(fmaf(tb, 3.6888794541139363f, -0.6931471805599453f));
        float tau = 0.5f * sig * sig;
        float rf[8], cf[8];
#pragma unroll
        for (int i = 0; i < 8; i++) {
            float fk = (float)rowIdx[i] * PI_N;
            rf[i] = expf(-fk * fk * tau);
            float fn = (float)colIdx[i] * PI_N;
            cf[i] = expf(-fn * fn * tau);
        }
#pragma unroll
        for (int i = 0; i < 8; i++) {
#pragma unroll
            for (int jh = 0; jh < 2; jh++) {
                float4 o;
                float* po = reinterpret_cast<float*>(&o);
#pragma unroll
                for (int jj = 0; jj < 4; jj++) {
                    int j = jh * 4 + jj;
                    float fade = rf[i] * cf[j];
                    if (fade < 0.01f) fade = 0.0f;
                    po[jj] = acc[i][j] * fmaf(fade, 0.999f, 0.001f);
                }
                *reinterpret_cast<float4*>(
                    &outImg[(size_t)rowIdx[i] * NDIM + colIdx[jh * 4]]) = o;
            }
        }
    } else {
#pragma unroll
        for (int i = 0; i < 8; i++) {
#pragma unroll
            for (int jh = 0; jh < 2; jh++) {
                float4 o = make_float4(acc[i][jh * 4 + 0], acc[i][jh * 4 + 1],
                                       acc[i][jh * 4 + 2], acc[i][jh * 4 + 3]);
                *reinterpret_cast<float4*>(
                    &outImg[(size_t)rowIdx[i] * NDIM + colIdx[jh * 4]]) = o;
            }
        }
    }
}

extern "C" void kernel_launch(void* const* d_in, const int* in_sizes, int n_in,
                              void* d_out, int out_size) {
    const float* x = (const float*)d_in[0];   // (128,3,256,256) fp32
    const float* t = (const float*)d_in[1];   // (128,) fp32
    float* out = (float*)d_out;               // (128,3,256,256) fp32

    init_C_kernel<<<(NDIM * NDIM + 255) / 256, 256>>>();

    dim3 blk(256, 1, 1);
    dim3 grd(2, 2, NIMG);
    dct_gemm<0><<<grd, blk>>>(x, nullptr, t);
    dct_gemm<1><<<grd, blk>>>(nullptr, nullptr, t);
    dct_gemm<2><<<grd, blk>>>(nullptr, nullptr, t);
    dct_gemm<3><<<grd, blk>>>(nullptr, out, t);
}

// round 6
// speedup vs baseline: 2.2293x; 1.7616x over previous
#include <cuda_runtime.h>
#include <cuda_bf16.h>
#include <cstdint>
#include <math.h>

#define NDIM 256
#define IMG (NDIM * NDIM)
#define NIMG (128 * 3)
#define BK 32
#define BM 128
#define BN 64
#define SA 40   // A smem row stride in bf16 (80B, 80/16=5 odd -> conflict-free ldmatrix)
#define SB 72   // B smem row stride in bf16 (144B, 144/16=9 odd -> conflict-free)

// ---- device globals (no allocation allowed) ----
__device__ __nv_bfloat16 g_Ch[NDIM * NDIM], g_Cl[NDIM * NDIM];
__device__ __nv_bfloat16 g_CTh[NDIM * NDIM], g_CTl[NDIM * NDIM];
__device__ __nv_bfloat16 g_t1h[NIMG * IMG], g_t1l[NIMG * IMG];
__device__ __nv_bfloat16 g_t2h[NIMG * IMG], g_t2l[NIMG * IMG];

// DCT-II orthonormal matrix, pre-split into bf16 hi/lo, plus its transpose.
__global__ void init_C_kernel() {
    int idx = blockIdx.x * blockDim.x + threadIdx.x;
    if (idx >= NDIM * NDIM) return;
    int k = idx >> 8, n = idx & 255;
    double v = cos(M_PI * ((double)n + 0.5) * (double)k / (double)NDIM);
    double s = (k == 0) ? sqrt(1.0 / NDIM) : sqrt(2.0 / NDIM);
    float f = (float)(v * s);
    __nv_bfloat16 h = __float2bfloat16_rn(f);
    __nv_bfloat16 l = __float2bfloat16_rn(f - __bfloat162float(h));
    g_Ch[k * NDIM + n] = h;
    g_Cl[k * NDIM + n] = l;
    g_CTh[n * NDIM + k] = h;
    g_CTl[n * NDIM + k] = l;
}

__device__ __forceinline__ uint32_t smem_u32(const void* p) {
    return (uint32_t)__cvta_generic_to_shared(p);
}

__device__ __forceinline__ void ldsm4(uint32_t* r, uint32_t addr) {
    asm volatile("ldmatrix.sync.aligned.m8n8.x4.shared.b16 {%0,%1,%2,%3}, [%4];"
                 : "=r"(r[0]), "=r"(r[1]), "=r"(r[2]), "=r"(r[3]) : "r"(addr));
}
__device__ __forceinline__ void ldsm4t(uint32_t* r, uint32_t addr) {
    asm volatile("ldmatrix.sync.aligned.m8n8.x4.trans.shared.b16 {%0,%1,%2,%3}, [%4];"
                 : "=r"(r[0]), "=r"(r[1]), "=r"(r[2]), "=r"(r[3]) : "r"(addr));
}
__device__ __forceinline__ void mma16816(float* d, const uint32_t* a, const uint32_t* b) {
    asm volatile(
        "mma.sync.aligned.m16n8k16.row.col.f32.bf16.bf16.f32 "
        "{%0,%1,%2,%3}, {%4,%5,%6,%7}, {%8,%9}, {%0,%1,%2,%3};"
        : "+f"(d[0]), "+f"(d[1]), "+f"(d[2]), "+f"(d[3])
        : "r"(a[0]), "r"(a[1]), "r"(a[2]), "r"(a[3]), "r"(b[0]), "r"(b[1]));
}

__device__ __forceinline__ void split_store_pair(__nv_bfloat16* baseH, __nv_bfloat16* baseL,
                                                 size_t off, float v0, float v1) {
    __nv_bfloat16 h0 = __float2bfloat16_rn(v0);
    __nv_bfloat16 h1 = __float2bfloat16_rn(v1);
    __nv_bfloat162 hp; hp.x = h0; hp.y = h1;
    __nv_bfloat162 lp;
    lp.x = __float2bfloat16_rn(v0 - __bfloat162float(h0));
    lp.y = __float2bfloat16_rn(v1 - __bfloat162float(h1));
    *reinterpret_cast<__nv_bfloat162*>(baseH + off) = hp;
    *reinterpret_cast<__nv_bfloat162*>(baseL + off) = lp;
}

// Batched Out = A*B per image (256x256x256), tensor-core bf16 hi/lo split.
// A smem layout [m][k] (ldmatrix), B smem layout [k][n] (ldmatrix.trans).
// MODE 0: T1 = C  * X    A: g_Ch/l     B: X (fp32, convert)  -> g_t1h/l
// MODE 1: Y  = T1 * C^T  A: g_t1h/l    B: g_CTh/l            -> g_t2h/l (mask)
// MODE 2: T2 = C^T* Y    A: g_CTh/l    B: g_t2h/l            -> g_t1h/l
// MODE 3: out= T2 * C    A: g_t1h/l    B: g_Ch/l             -> out (fp32)
template <int MODE>
__global__ void __launch_bounds__(256, 2) dct_mma(const float* __restrict__ xin,
                                                  float* __restrict__ gout,
                                                  const float* __restrict__ tarr) {
    __shared__ __align__(16) __nv_bfloat16 sAh[BM * SA], sAl[BM * SA];
    __shared__ __align__(16) __nv_bfloat16 sBh[BK * SB], sBl[BK * SB];

    const int img = blockIdx.z;
    const int m0 = blockIdx.y * BM;
    const int n0 = blockIdx.x * BN;
    const int tid = threadIdx.x;
    const int wid = tid >> 5;
    const int lane = tid & 31;
    const int wm = wid & 3;   // 4 warps along m
    const int wn = wid >> 2;  // 2 warps along n

    // A source (always bf16 hi/lo, row-major [row][k], stride 256)
    const __nv_bfloat16 *aH, *aL;
    if constexpr (MODE == 0)      { aH = g_Ch;                       aL = g_Cl; }
    else if constexpr (MODE == 1) { aH = g_t1h + (size_t)img * IMG;  aL = g_t1l + (size_t)img * IMG; }
    else if constexpr (MODE == 2) { aH = g_CTh;                      aL = g_CTl; }
    else                          { aH = g_t1h + (size_t)img * IMG;  aL = g_t1l + (size_t)img * IMG; }

    // B source: MODE 0 is fp32 X; others bf16 [k][n], stride 256
    const __nv_bfloat16 *bH = nullptr, *bL = nullptr;
    const float* bF = nullptr;
    if constexpr (MODE == 0)      { bF = xin + (size_t)img * IMG; }
    else if constexpr (MODE == 1) { bH = g_CTh;                      bL = g_CTl; }
    else if constexpr (MODE == 2) { bH = g_t2h + (size_t)img * IMG;  bL = g_t2l + (size_t)img * IMG; }
    else                          { bH = g_Ch;                       bL = g_Cl; }

    float d[2][4][4];  // [m16 tile][n8 tile][frag]
#pragma unroll
    for (int i = 0; i < 2; i++)
#pragma unroll
        for (int j = 0; j < 4; j++)
#pragma unroll
            for (int q = 0; q < 4; q++) d[i][j][q] = 0.0f;

    const uint32_t sAhB = smem_u32(sAh), sAlB = smem_u32(sAl);
    const uint32_t sBhB = smem_u32(sBh), sBlB = smem_u32(sBl);

    for (int k0 = 0; k0 < NDIM; k0 += BK) {
        // ---- A: 128x32 bf16 x2 arrays; 512 uint4 per array, 2/thread ----
#pragma unroll
        for (int u = 0; u < 2; u++) {
            int idx = tid + 256 * u;
            int m = idx >> 2;
            int k8 = (idx & 3) * 8;
            size_t off = (size_t)(m0 + m) * NDIM + k0 + k8;
            *reinterpret_cast<uint4*>(&sAh[m * SA + k8]) =
                *reinterpret_cast<const uint4*>(aH + off);
            *reinterpret_cast<uint4*>(&sAl[m * SA + k8]) =
                *reinterpret_cast<const uint4*>(aL + off);
        }
        // ---- B: 32x64 ----
        if constexpr (MODE == 0) {
#pragma unroll
            for (int u = 0; u < 2; u++) {
                int idx = tid + 256 * u;
                int k = idx >> 4;
                int n4 = (idx & 15) * 4;
                float4 v = *reinterpret_cast<const float4*>(bF + (size_t)(k0 + k) * NDIM + n0 + n4);
                __nv_bfloat16 h0 = __float2bfloat16_rn(v.x), h1 = __float2bfloat16_rn(v.y);
                __nv_bfloat16 h2 = __float2bfloat16_rn(v.z), h3 = __float2bfloat16_rn(v.w);
                __nv_bfloat162 hp0; hp0.x = h0; hp0.y = h1;
                __nv_bfloat162 hp1; hp1.x = h2; hp1.y = h3;
                __nv_bfloat162 lp0, lp1;
                lp0.x = __float2bfloat16_rn(v.x - __bfloat162float(h0));
                lp0.y = __float2bfloat16_rn(v.y - __bfloat162float(h1));
                lp1.x = __float2bfloat16_rn(v.z - __bfloat162float(h2));
                lp1.y = __float2bfloat16_rn(v.w - __bfloat162float(h3));
                *reinterpret_cast<__nv_bfloat162*>(&sBh[k * SB + n4]) = hp0;
                *reinterpret_cast<__nv_bfloat162*>(&sBh[k * SB + n4 + 2]) = hp1;
                *reinterpret_cast<__nv_bfloat162*>(&sBl[k * SB + n4]) = lp0;
                *reinterpret_cast<__nv_bfloat162*>(&sBl[k * SB + n4 + 2]) = lp1;
            }
        } else {
            int k = tid >> 3;
            int n8 = (tid & 7) * 8;
            size_t off = (size_t)(k0 + k) * NDIM + n0 + n8;
            *reinterpret_cast<uint4*>(&sBh[k * SB + n8]) =
                *reinterpret_cast<const uint4*>(bH + off);
            *reinterpret_cast<uint4*>(&sBl[k * SB + n8]) =
                *reinterpret_cast<const uint4*>(bL + off);
        }
        __syncthreads();

#pragma unroll
        for (int kk = 0; kk < BK; kk += 16) {
            // A fragments (2 m16 tiles), hi and lo
            uint32_t fAh[2][4], fAl[2][4];
#pragma unroll
            for (int mt = 0; mt < 2; mt++) {
                int row = wm * 32 + mt * 16 + (lane & 7) + ((lane >> 3) & 1) * 8;
                int col = kk + (lane >> 4) * 8;
                uint32_t byteoff = (uint32_t)(row * SA + col) * 2;
                ldsm4(fAh[mt], sAhB + byteoff);
                ldsm4(fAl[mt], sAlB + byteoff);
            }
            // B fragments (4 n8 tiles via 2 x4.trans), hi and lo
            uint32_t fBh[4][2], fBl[4][2];
#pragma unroll
            for (int nt2 = 0; nt2 < 2; nt2++) {
                int row = kk + (lane & 7) + ((lane >> 3) & 1) * 8;
                int col = wn * 32 + nt2 * 16 + (lane >> 4) * 8;
                uint32_t byteoff = (uint32_t)(row * SB + col) * 2;
                uint32_t r[4];
                ldsm4t(r, sBhB + byteoff);
                fBh[nt2 * 2][0] = r[0]; fBh[nt2 * 2][1] = r[1];
                fBh[nt2 * 2 + 1][0] = r[2]; fBh[nt2 * 2 + 1][1] = r[3];
                ldsm4t(r, sBlB + byteoff);
                fBl[nt2 * 2][0] = r[0]; fBl[nt2 * 2][1] = r[1];
                fBl[nt2 * 2 + 1][0] = r[2]; fBl[nt2 * 2 + 1][1] = r[3];
            }
#pragma unroll
            for (int mt = 0; mt < 2; mt++)
#pragma unroll
                for (int nt = 0; nt < 4; nt++) {
                    mma16816(d[mt][nt], fAh[mt], fBh[nt]);
                    mma16816(d[mt][nt], fAh[mt], fBl[nt]);
                    mma16816(d[mt][nt], fAl[mt], fBh[nt]);
                }
        }
        __syncthreads();
    }

    // ---- epilogue ----
    const int g = lane >> 2, q = lane & 3;

    if constexpr (MODE == 1) {
        const float PI_N = 0.01227184630308513f;  // pi/256
        float tb = tarr[img / 3];
        float sig = expf(fmaf(tb, 3.6888794541139363f, -0.6931471805599453f));
        float tau = 0.5f * sig * sig;
        float rf[2][2], cf[4][2];
#pragma unroll
        for (int mt = 0; mt < 2; mt++) {
            int r0 = m0 + wm * 32 + mt * 16 + g;
            float f0 = (float)r0 * PI_N, f1 = (float)(r0 + 8) * PI_N;
            rf[mt][0] = expf(-f0 * f0 * tau);
            rf[mt][1] = expf(-f1 * f1 * tau);
        }
#pragma unroll
        for (int nt = 0; nt < 4; nt++) {
            int c0 = n0 + wn * 32 + nt * 8 + q * 2;
            float f0 = (float)c0 * PI_N, f1 = (float)(c0 + 1) * PI_N;
            cf[nt][0] = expf(-f0 * f0 * tau);
            cf[nt][1] = expf(-f1 * f1 * tau);
        }
        __nv_bfloat16* oH = g_t2h + (size_t)img * IMG;
        __nv_bfloat16* oL = g_t2l + (size_t)img * IMG;
#pragma unroll
        for (int mt = 0; mt < 2; mt++)
#pragma unroll
            for (int nt = 0; nt < 4; nt++) {
                int r0 = m0 + wm * 32 + mt * 16 + g;
                int c0 = n0 + wn * 32 + nt * 8 + q * 2;
#pragma unroll
                for (int rh = 0; rh < 2; rh++) {
                    int row = r0 + rh * 8;
                    float fa0 = rf[mt][rh] * cf[nt][0];
                    float fa1 = rf[mt][rh] * cf[nt][1];
                    if (fa0 < 0.01f) fa0 = 0.0f;
                    if (fa1 < 0.01f) fa1 = 0.0f;
                    float v0 = d[mt][nt][rh * 2 + 0] * fmaf(fa0, 0.999f, 0.001f);
                    float v1 = d[mt][nt][rh * 2 + 1] * fmaf(fa1, 0.999f, 0.001f);
                    split_store_pair(oH, oL, (size_t)row * NDIM + c0, v0, v1);
                }
            }
    } else if constexpr (MODE == 3) {
        float* outImg = gout + (size_t)img * IMG;
#pragma unroll
        for (int mt = 0; mt < 2; mt++)
#pragma unroll
            for (int nt = 0; nt < 4; nt++) {
                int r0 = m0 + wm * 32 + mt * 16 + g;
                int c0 = n0 + wn * 32 + nt * 8 + q * 2;
#pragma unroll
                for (int rh = 0; rh < 2; rh++) {
                    float2 o = make_float2(d[mt][nt][rh * 2 + 0], d[mt][nt][rh * 2 + 1]);
                    *reinterpret_cast<float2*>(&outImg[(size_t)(r0 + rh * 8) * NDIM + c0]) = o;
                }
            }
    } else {
        __nv_bfloat16* oH = g_t1h + (size_t)img * IMG;
        __nv_bfloat16* oL = g_t1l + (size_t)img * IMG;
#pragma unroll
        for (int mt = 0; mt < 2; mt++)
#pragma unroll
            for (int nt = 0; nt < 4; nt++) {
                int r0 = m0 + wm * 32 + mt * 16 + g;
                int c0 = n0 + wn * 32 + nt * 8 + q * 2;
#pragma unroll
                for (int rh = 0; rh < 2; rh++) {
                    split_store_pair(oH, oL, (size_t)(r0 + rh * 8) * NDIM + c0,
                                     d[mt][nt][rh * 2 + 0], d[mt][nt][rh * 2 + 1]);
                }
            }
    }
}

extern "C" void kernel_launch(void* const* d_in, const int* in_sizes, int n_in,
                              void* d_out, int out_size) {
    const float* x = (const float*)d_in[0];   // (128,3,256,256) fp32
    const float* t = (const float*)d_in[1];   // (128,) fp32
    float* out = (float*)d_out;               // (128,3,256,256) fp32

    init_C_kernel<<<(NDIM * NDIM + 255) / 256, 256>>>();

    dim3 blk(256, 1, 1);
    dim3 grd(NDIM / BN, NDIM / BM, NIMG);  // (4, 2, 384)
    dct_mma<0><<<grd, blk>>>(x, nullptr, t);
    dct_mma<1><<<grd, blk>>>(nullptr, nullptr, t);
    dct_mma<2><<<grd, blk>>>(nullptr, nullptr, t);
    dct_mma<3><<<grd, blk>>>(nullptr, out, t);
}

// round 7
// speedup vs baseline: 2.7014x; 1.2117x over previous
#include <cuda_runtime.h>
#include <cuda_bf16.h>
#include <cstdint>
#include <math.h>

#define NDIM 256
#define IMG (NDIM * NDIM)
#define NIMG (128 * 3)
#define BM 128
#define BN 128
#define BK 32
#define SA 40    // A smem row stride (bf16): 80B = 5*16B odd -> conflict-free ldmatrix
#define SBN 136  // B smem row stride (bf16): 272B = 17*16B odd -> conflict-free
#define NITER (NDIM / BK)  // 8

#define A_BYTES (BM * SA * 2)                  // 10240
#define B_BYTES (BK * SBN * 2)                 // 8704
#define BUF_BYTES (2 * A_BYTES + 2 * B_BYTES)  // 37888
#define SMEM_BYTES (2 * BUF_BYTES)             // 75776

// ---- device globals (no allocation allowed) ----
__device__ __nv_bfloat16 g_Ch[IMG], g_Cl[IMG];
__device__ __nv_bfloat16 g_CTh[IMG], g_CTl[IMG];
__device__ __nv_bfloat16 g_t1h[NIMG * IMG], g_t1l[NIMG * IMG];
__device__ __nv_bfloat16 g_t2h[NIMG * IMG], g_t2l[NIMG * IMG];

// DCT-II orthonormal matrix, pre-split into bf16 hi/lo, plus transpose.
__global__ void init_C_kernel() {
    int idx = blockIdx.x * blockDim.x + threadIdx.x;
    if (idx >= IMG) return;
    int k = idx >> 8, n = idx & 255;
    double v = cos(M_PI * ((double)n + 0.5) * (double)k / (double)NDIM);
    double s = (k == 0) ? sqrt(1.0 / NDIM) : sqrt(2.0 / NDIM);
    float f = (float)(v * s);
    __nv_bfloat16 h = __float2bfloat16_rn(f);
    __nv_bfloat16 l = __float2bfloat16_rn(f - __bfloat162float(h));
    g_Ch[k * NDIM + n] = h;
    g_Cl[k * NDIM + n] = l;
    g_CTh[n * NDIM + k] = h;
    g_CTl[n * NDIM + k] = l;
}

// Pre-split X (fp32) into bf16 hi/lo pairs stored in g_t2 (free at stage 0).
__global__ void split_x_kernel(const float* __restrict__ x) {
    size_t i = ((size_t)blockIdx.x * 256 + threadIdx.x) * 4;
    float4 v = *reinterpret_cast<const float4*>(x + i);
    __nv_bfloat162 h0, h1, l0, l1;
    h0.x = __float2bfloat16_rn(v.x); h0.y = __float2bfloat16_rn(v.y);
    h1.x = __float2bfloat16_rn(v.z); h1.y = __float2bfloat16_rn(v.w);
    l0.x = __float2bfloat16_rn(v.x - __bfloat162float(h0.x));
    l0.y = __float2bfloat16_rn(v.y - __bfloat162float(h0.y));
    l1.x = __float2bfloat16_rn(v.z - __bfloat162float(h1.x));
    l1.y = __float2bfloat16_rn(v.w - __bfloat162float(h1.y));
    *reinterpret_cast<__nv_bfloat162*>(g_t2h + i) = h0;
    *reinterpret_cast<__nv_bfloat162*>(g_t2h + i + 2) = h1;
    *reinterpret_cast<__nv_bfloat162*>(g_t2l + i) = l0;
    *reinterpret_cast<__nv_bfloat162*>(g_t2l + i + 2) = l1;
}

__device__ __forceinline__ uint32_t smem_u32(const void* p) {
    return (uint32_t)__cvta_generic_to_shared(p);
}
__device__ __forceinline__ void cpa16(uint32_t s, const void* g) {
    asm volatile("cp.async.cg.shared.global [%0], [%1], 16;" :: "r"(s), "l"(g));
}
__device__ __forceinline__ void ldsm4(uint32_t* r, uint32_t addr) {
    asm volatile("ldmatrix.sync.aligned.m8n8.x4.shared.b16 {%0,%1,%2,%3}, [%4];"
                 : "=r"(r[0]), "=r"(r[1]), "=r"(r[2]), "=r"(r[3]) : "r"(addr));
}
__device__ __forceinline__ void ldsm4t(uint32_t* r, uint32_t addr) {
    asm volatile("ldmatrix.sync.aligned.m8n8.x4.trans.shared.b16 {%0,%1,%2,%3}, [%4];"
                 : "=r"(r[0]), "=r"(r[1]), "=r"(r[2]), "=r"(r[3]) : "r"(addr));
}
__device__ __forceinline__ void mma16816(float* d, const uint32_t* a, const uint32_t* b) {
    asm volatile(
        "mma.sync.aligned.m16n8k16.row.col.f32.bf16.bf16.f32 "
        "{%0,%1,%2,%3}, {%4,%5,%6,%7}, {%8,%9}, {%0,%1,%2,%3};"
        : "+f"(d[0]), "+f"(d[1]), "+f"(d[2]), "+f"(d[3])
        : "r"(a[0]), "r"(a[1]), "r"(a[2]), "r"(a[3]), "r"(b[0]), "r"(b[1]));
}
__device__ __forceinline__ void split_store_pair(__nv_bfloat16* baseH, __nv_bfloat16* baseL,
                                                 size_t off, float v0, float v1) {
    __nv_bfloat16 h0 = __float2bfloat16_rn(v0);
    __nv_bfloat16 h1 = __float2bfloat16_rn(v1);
    __nv_bfloat162 hp; hp.x = h0; hp.y = h1;
    __nv_bfloat162 lp;
    lp.x = __float2bfloat16_rn(v0 - __bfloat162float(h0));
    lp.y = __float2bfloat16_rn(v1 - __bfloat162float(h1));
    *reinterpret_cast<__nv_bfloat162*>(baseH + off) = hp;
    *reinterpret_cast<__nv_bfloat162*>(baseL + off) = lp;
}

// Batched Out = A*B per image (256^3), bf16 hi/lo 3-term split, cp.async pipeline.
// A smem [m][k] (ldmatrix), B smem [k][n] (ldmatrix.trans). All operands bf16 pairs.
// MODE 0: T1 = C  * X     A: g_C      B: g_t2 (X presplit) -> g_t1
// MODE 1: Y  = T1 * C^T   A: g_t1     B: g_CT              -> g_t2 (mask)
// MODE 2: T2 = C^T* Y     A: g_CT     B: g_t2              -> g_t1
// MODE 3: out= T2 * C     A: g_t1     B: g_C               -> out (fp32)
template <int MODE>
__global__ void __launch_bounds__(256, 2) dct_mma(float* __restrict__ gout,
                                                  const float* __restrict__ tarr) {
    extern __shared__ __align__(16) unsigned char smem[];

    const int img = blockIdx.z;
    const int m0 = blockIdx.y * BM;
    const int n0 = blockIdx.x * BN;
    const int tid = threadIdx.x;
    const int wid = tid >> 5;
    const int lane = tid & 31;
    const int wm = wid & 3;   // 4 warps along m (32 rows each)
    const int wn = wid >> 2;  // 2 warps along n (64 cols each)

    const __nv_bfloat16 *aH, *aL, *bH, *bL;
    if constexpr (MODE == 0)      { aH = g_Ch;  aL = g_Cl;
                                    bH = g_t2h + (size_t)img * IMG; bL = g_t2l + (size_t)img * IMG; }
    else if constexpr (MODE == 1) { aH = g_t1h + (size_t)img * IMG; aL = g_t1l + (size_t)img * IMG;
                                    bH = g_CTh; bL = g_CTl; }
    else if constexpr (MODE == 2) { aH = g_CTh; aL = g_CTl;
                                    bH = g_t2h + (size_t)img * IMG; bL = g_t2l + (size_t)img * IMG; }
    else                          { aH = g_t1h + (size_t)img * IMG; aL = g_t1l + (size_t)img * IMG;
                                    bH = g_Ch;  bL = g_Cl; }

    const uint32_t smem_base = smem_u32(smem);

    // issue cp.async fills for k-slab k0 into buffer b
    auto issue = [&](int k0, int b) {
        uint32_t base = smem_base + b * BUF_BYTES;
#pragma unroll
        for (int u = 0; u < 2; u++) {
            int idx = tid + 256 * u;
            int m = idx >> 2, k8 = (idx & 3) * 8;
            size_t goff = (size_t)(m0 + m) * NDIM + k0 + k8;
            uint32_t soff = (uint32_t)(m * SA + k8) * 2;
            cpa16(base + soff, aH + goff);
            cpa16(base + A_BYTES + soff, aL + goff);
        }
#pragma unroll
        for (int u = 0; u < 2; u++) {
            int idx = tid + 256 * u;
            int k = idx >> 4, n8 = (idx & 15) * 8;
            size_t goff = (size_t)(k0 + k) * NDIM + n0 + n8;
            uint32_t soff = (uint32_t)(k * SBN + n8) * 2;
            cpa16(base + 2 * A_BYTES + soff, bH + goff);
            cpa16(base + 2 * A_BYTES + B_BYTES + soff, bL + goff);
        }
    };

    float d[2][8][4];
#pragma unroll
    for (int i = 0; i < 2; i++)
#pragma unroll
        for (int j = 0; j < 8; j++)
#pragma unroll
            for (int q = 0; q < 4; q++) d[i][j][q] = 0.0f;

    issue(0, 0);
    asm volatile("cp.async.commit_group;" ::: "memory");
    issue(BK, 1);
    asm volatile("cp.async.commit_group;" ::: "memory");

    for (int it = 0; it < NITER; it++) {
        asm volatile("cp.async.wait_group 1;" ::: "memory");
        __syncthreads();

        const int b = it & 1;
        const uint32_t ahB = smem_base + b * BUF_BYTES;
        const uint32_t alB = ahB + A_BYTES;
        const uint32_t bhB = ahB + 2 * A_BYTES;
        const uint32_t blB = bhB + B_BYTES;

#pragma unroll
        for (int kk = 0; kk < BK; kk += 16) {
            uint32_t fAh[2][4], fAl[2][4];
#pragma unroll
            for (int mt = 0; mt < 2; mt++) {
                int row = wm * 32 + mt * 16 + (lane & 7) + ((lane >> 3) & 1) * 8;
                int col = kk + (lane >> 4) * 8;
                uint32_t off = (uint32_t)(row * SA + col) * 2;
                ldsm4(fAh[mt], ahB + off);
                ldsm4(fAl[mt], alB + off);
            }
#pragma unroll
            for (int nt2 = 0; nt2 < 4; nt2++) {
                int row = kk + (lane & 7) + ((lane >> 3) & 1) * 8;
                int col = wn * 64 + nt2 * 16 + (lane >> 4) * 8;
                uint32_t off = (uint32_t)(row * SBN + col) * 2;
                uint32_t rh[4], rl[4];
                ldsm4t(rh, bhB + off);
                ldsm4t(rl, blB + off);
#pragma unroll
                for (int mt = 0; mt < 2; mt++) {
                    mma16816(d[mt][nt2 * 2 + 0], fAh[mt], &rh[0]);
                    mma16816(d[mt][nt2 * 2 + 0], fAh[mt], &rl[0]);
                    mma16816(d[mt][nt2 * 2 + 0], fAl[mt], &rh[0]);
                    mma16816(d[mt][nt2 * 2 + 1], fAh[mt], &rh[2]);
                    mma16816(d[mt][nt2 * 2 + 1], fAh[mt], &rl[2]);
                    mma16816(d[mt][nt2 * 2 + 1], fAl[mt], &rh[2]);
                }
            }
        }
        __syncthreads();
        if (it + 2 < NITER) issue((it + 2) * BK, b);
        asm volatile("cp.async.commit_group;" ::: "memory");
    }

    // ---- epilogue ----
    const int g = lane >> 2, q = lane & 3;

    if constexpr (MODE == 1) {
        const float PI_N = 0.01227184630308513f;  // pi/256
        float tb = tarr[img / 3];
        float sig = expf(fmaf(tb, 3.6888794541139363f, -0.6931471805599453f));
        float tau = 0.5f * sig * sig;
        float rf[2][2], cf[8][2];
#pragma unroll
        for (int mt = 0; mt < 2; mt++) {
            int r0 = m0 + wm * 32 + mt * 16 + g;
            float f0 = (float)r0 * PI_N, f1 = (float)(r0 + 8) * PI_N;
            rf[mt][0] = expf(-f0 * f0 * tau);
            rf[mt][1] = expf(-f1 * f1 * tau);
        }
#pragma unroll
        for (int nt = 0; nt < 8; nt++) {
            int c0 = n0 + wn * 64 + nt * 8 + q * 2;
            float f0 = (float)c0 * PI_N, f1 = (float)(c0 + 1) * PI_N;
            cf[nt][0] = expf(-f0 * f0 * tau);
            cf[nt][1] = expf(-f1 * f1 * tau);
        }
        __nv_bfloat16* oH = g_t2h + (size_t)img * IMG;
        __nv_bfloat16* oL = g_t2l + (size_t)img * IMG;
#pragma unroll
        for (int mt = 0; mt < 2; mt++)
#pragma unroll
            for (int nt = 0; nt < 8; nt++) {
                int r0 = m0 + wm * 32 + mt * 16 + g;
                int c0 = n0 + wn * 64 + nt * 8 + q * 2;
#pragma unroll
                for (int rh = 0; rh < 2; rh++) {
                    float fa0 = rf[mt][rh] * cf[nt][0];
                    float fa1 = rf[mt][rh] * cf[nt][1];
                    if (fa0 < 0.01f) fa0 = 0.0f;
                    if (fa1 < 0.01f) fa1 = 0.0f;
                    float v0 = d[mt][nt][rh * 2 + 0] * fmaf(fa0, 0.999f, 0.001f);
                    float v1 = d[mt][nt][rh * 2 + 1] * fmaf(fa1, 0.999f, 0.001f);
                    split_store_pair(oH, oL, (size_t)(r0 + rh * 8) * NDIM + c0, v0, v1);
                }
            }
    } else if constexpr (MODE == 3) {
        float* outImg = gout + (size_t)img * IMG;
#pragma unroll
        for (int mt = 0; mt < 2; mt++)
#pragma unroll
            for (int nt = 0; nt < 8; nt++) {
                int r0 = m0 + wm * 32 + mt * 16 + g;
                int c0 = n0 + wn * 64 + nt * 8 + q * 2;
#pragma unroll
                for (int rh = 0; rh < 2; rh++) {
                    float2 o = make_float2(d[mt][nt][rh * 2 + 0], d[mt][nt][rh * 2 + 1]);
                    *reinterpret_cast<float2*>(&outImg[(size_t)(r0 + rh * 8) * NDIM + c0]) = o;
                }
            }
    } else {
        __nv_bfloat16* oH = g_t1h + (size_t)img * IMG;
        __nv_bfloat16* oL = g_t1l + (size_t)img * IMG;
#pragma unroll
        for (int mt = 0; mt < 2; mt++)
#pragma unroll
            for (int nt = 0; nt < 8; nt++) {
                int r0 = m0 + wm * 32 + mt * 16 + g;
                int c0 = n0 + wn * 64 + nt * 8 + q * 2;
#pragma unroll
                for (int rh = 0; rh < 2; rh++) {
                    split_store_pair(oH, oL, (size_t)(r0 + rh * 8) * NDIM + c0,
                                     d[mt][nt][rh * 2 + 0], d[mt][nt][rh * 2 + 1]);
                }
            }
    }
}

extern "C" void kernel_launch(void* const* d_in, const int* in_sizes, int n_in,
                              void* d_out, int out_size) {
    const float* x = (const float*)d_in[0];   // (128,3,256,256) fp32
    const float* t = (const float*)d_in[1];   // (128,) fp32
    float* out = (float*)d_out;               // (128,3,256,256) fp32

    // dynamic smem opt-in (idempotent host-side attribute set; no allocation)
    cudaFuncSetAttribute(dct_mma<0>, cudaFuncAttributeMaxDynamicSharedMemorySize, SMEM_BYTES);
    cudaFuncSetAttribute(dct_mma<1>, cudaFuncAttributeMaxDynamicSharedMemorySize, SMEM_BYTES);
    cudaFuncSetAttribute(dct_mma<2>, cudaFuncAttributeMaxDynamicSharedMemorySize, SMEM_BYTES);
    cudaFuncSetAttribute(dct_mma<3>, cudaFuncAttributeMaxDynamicSharedMemorySize, SMEM_BYTES);

    init_C_kernel<<<(IMG + 255) / 256, 256>>>();
    split_x_kernel<<<(NIMG * IMG) / (256 * 4), 256>>>(x);

    dim3 blk(256, 1, 1);
    dim3 grd(NDIM / BN, NDIM / BM, NIMG);  // (2, 2, 384)
    dct_mma<0><<<grd, blk, SMEM_BYTES>>>(nullptr, t);
    dct_mma<1><<<grd, blk, SMEM_BYTES>>>(nullptr, t);
    dct_mma<2><<<grd, blk, SMEM_BYTES>>>(nullptr, t);
    dct_mma<3><<<grd, blk, SMEM_BYTES>>>(out, t);
}

// round 11
// speedup vs baseline: 3.8385x; 1.4210x over previous
#include <cuda_runtime.h>
#include <cuda_bf16.h>
#include <cstdint>
#include <math.h>

#define NDIM 256
#define IMG (NDIM * NDIM)
#define NIMG (128 * 3)
#define BM 128
#define BN 128
#define BK 32
#define SA 40    // A smem row stride (bf16): 80B = 5*16B odd -> conflict-free ldmatrix
#define SBN 136  // B smem row stride (bf16): 272B = 17*16B odd -> conflict-free

#define A_BYTES (BM * SA * 2)                  // 10240
#define B_BYTES (BK * SBN * 2)                 // 8704
#define BUF_BYTES (2 * A_BYTES + 2 * B_BYTES)  // 37888
#define SMEM_BYTES (2 * BUF_BYTES)             // 75776

// ---- device globals (no allocation allowed) ----
__device__ __nv_bfloat16 g_Ch[IMG], g_Cl[IMG];
__device__ __nv_bfloat16 g_CTh[IMG], g_CTl[IMG];
__device__ __nv_bfloat16 g_t1h[NIMG * IMG], g_t1l[NIMG * IMG];
__device__ __nv_bfloat16 g_t2h[NIMG * IMG], g_t2l[NIMG * IMG];

// DCT-II orthonormal matrix, pre-split into bf16 hi/lo, plus transpose.
__global__ void init_C_kernel() {
    int idx = blockIdx.x * blockDim.x + threadIdx.x;
    if (idx >= IMG) return;
    int k = idx >> 8, n = idx & 255;
    double v = cos(M_PI * ((double)n + 0.5) * (double)k / (double)NDIM);
    double s = (k == 0) ? sqrt(1.0 / NDIM) : sqrt(2.0 / NDIM);
    float f = (float)(v * s);
    __nv_bfloat16 h = __float2bfloat16_rn(f);
    __nv_bfloat16 l = __float2bfloat16_rn(f - __bfloat162float(h));
    g_Ch[k * NDIM + n] = h;
    g_Cl[k * NDIM + n] = l;
    g_CTh[n * NDIM + k] = h;
    g_CTl[n * NDIM + k] = l;
}

// Pre-split X (fp32) into bf16 hi/lo pairs stored in g_t2 (free at stage 0).
__global__ void split_x_kernel(const float* __restrict__ x) {
    size_t i = ((size_t)blockIdx.x * 256 + threadIdx.x) * 4;
    float4 v = *reinterpret_cast<const float4*>(x + i);
    __nv_bfloat162 h0, h1, l0, l1;
    h0.x = __float2bfloat16_rn(v.x); h0.y = __float2bfloat16_rn(v.y);
    h1.x = __float2bfloat16_rn(v.z); h1.y = __float2bfloat16_rn(v.w);
    l0.x = __float2bfloat16_rn(v.x - __bfloat162float(h0.x));
    l0.y = __float2bfloat16_rn(v.y - __bfloat162float(h0.y));
    l1.x = __float2bfloat16_rn(v.z - __bfloat162float(h1.x));
    l1.y = __float2bfloat16_rn(v.w - __bfloat162float(h1.y));
    *reinterpret_cast<__nv_bfloat162*>(g_t2h + i) = h0;
    *reinterpret_cast<__nv_bfloat162*>(g_t2h + i + 2) = h1;
    *reinterpret_cast<__nv_bfloat162*>(g_t2l + i) = l0;
    *reinterpret_cast<__nv_bfloat162*>(g_t2l + i + 2) = l1;
}

__device__ __forceinline__ uint32_t smem_u32(const void* p) {
    return (uint32_t)__cvta_generic_to_shared(p);
}
__device__ __forceinline__ void cpa16(uint32_t s, const void* g) {
    asm volatile("cp.async.cg.shared.global [%0], [%1], 16;" :: "r"(s), "l"(g));
}
__device__ __forceinline__ void ldsm4(uint32_t* r, uint32_t addr) {
    asm volatile("ldmatrix.sync.aligned.m8n8.x4.shared.b16 {%0,%1,%2,%3}, [%4];"
                 : "=r"(r[0]), "=r"(r[1]), "=r"(r[2]), "=r"(r[3]) : "r"(addr));
}
__device__ __forceinline__ void ldsm4t(uint32_t* r, uint32_t addr) {
    asm volatile("ldmatrix.sync.aligned.m8n8.x4.trans.shared.b16 {%0,%1,%2,%3}, [%4];"
                 : "=r"(r[0]), "=r"(r[1]), "=r"(r[2]), "=r"(r[3]) : "r"(addr));
}
__device__ __forceinline__ void mma16816(float* d, const uint32_t* a, const uint32_t* b) {
    asm volatile(
        "mma.sync.aligned.m16n8k16.row.col.f32.bf16.bf16.f32 "
        "{%0,%1,%2,%3}, {%4,%5,%6,%7}, {%8,%9}, {%0,%1,%2,%3};"
        : "+f"(d[0]), "+f"(d[1]), "+f"(d[2]), "+f"(d[3])
        : "r"(a[0]), "r"(a[1]), "r"(a[2]), "r"(a[3]), "r"(b[0]), "r"(b[1]));
}
__device__ __forceinline__ void split_store_pair(__nv_bfloat16* baseH, __nv_bfloat16* baseL,
                                                 size_t off, float v0, float v1) {
    __nv_bfloat16 h0 = __float2bfloat16_rn(v0);
    __nv_bfloat16 h1 = __float2bfloat16_rn(v1);
    __nv_bfloat162 hp; hp.x = h0; hp.y = h1;
    __nv_bfloat162 lp;
    lp.x = __float2bfloat16_rn(v0 - __bfloat162float(h0));
    lp.y = __float2bfloat16_rn(v1 - __bfloat162float(h1));
    *reinterpret_cast<__nv_bfloat162*>(baseH + off) = hp;
    *reinterpret_cast<__nv_bfloat162*>(baseL + off) = lp;
}

// Frequency cutoff: entries (k,n) with fade >= 0.01 require k,n < Km.
// Km = (256/pi)*sqrt(2 ln 100)/sigma = 247.31/sigma (+2 conservative margin).
// Identical fp sequence in all stages -> identical Km everywhere.
__device__ __forceinline__ int compute_Km(float tb) {
    float sig = expf(fmaf(tb, 3.6888794541139363f, -0.6931471805599453f));
    int km = (int)(247.32f / sig) + 2;
    return km > NDIM ? NDIM : km;
}

// Batched Out = A*B per image (256^3), bf16 hi/lo 3-term split, cp.async pipeline.
// Exact frequency sparsity: out = 0.001*X + 0.999*C^T(fadeT . dct)C, fadeT zero
// outside [0,Km)^2 -> tile skips + truncated K-loops (all exact).
// MODE 0: T1 = C  * X     A: g_C      B: g_t2 (X presplit) -> g_t1  [rows < Km]
// MODE 1: Y  = T1 * C^T   A: g_t1     B: g_CT              -> g_t2  [tiles < Km; mask 0.999*fadeT]
// MODE 2: T2 = C^T* Y     A: g_CT    B: g_t2              -> g_t1  [cols < Km; K < Km32]
// MODE 3: out= T2 * C     A: g_t1     B: g_C               -> out   [K < Km32; +0.001*X]
template <int MODE>
__global__ void __launch_bounds__(256, 2) dct_mma(const float* __restrict__ xin,
                                                  float* __restrict__ gout,
                                                  const float* __restrict__ tarr) {
    extern __shared__ __align__(16) unsigned char smem[];

    const int img = blockIdx.z;
    const int m0 = blockIdx.y * BM;
    const int n0 = blockIdx.x * BN;

    const int Km = compute_Km(tarr[img / 3]);
    if constexpr (MODE == 0) { if (m0 >= Km) return; }
    if constexpr (MODE == 1) { if (m0 >= Km || n0 >= Km) return; }
    if constexpr (MODE == 2) { if (n0 >= Km) return; }
    int kend;
    if constexpr (MODE >= 2) {
        int km32 = (Km + 31) & ~31;
        kend = km32 > NDIM ? NDIM : km32;
    } else {
        kend = NDIM;
    }
    const int niter = kend / BK;

    const int tid = threadIdx.x;
    const int wid = tid >> 5;
    const int lane = tid & 31;
    const int wm = wid & 3;   // 4 warps along m (32 rows each)
    const int wn = wid >> 2;  // 2 warps along n (64 cols each)

    const __nv_bfloat16 *aH, *aL, *bH, *bL;
    if constexpr (MODE == 0)      { aH = g_Ch;  aL = g_Cl;
                                    bH = g_t2h + (size_t)img * IMG; bL = g_t2l + (size_t)img * IMG; }
    else if constexpr (MODE == 1) { aH = g_t1h + (size_t)img * IMG; aL = g_t1l + (size_t)img * IMG;
                                    bH = g_CTh; bL = g_CTl; }
    else if constexpr (MODE == 2) { aH = g_CTh; aL = g_CTl;
                                    bH = g_t2h + (size_t)img * IMG; bL = g_t2l + (size_t)img * IMG; }
    else                          { aH = g_t1h + (size_t)img * IMG; aL = g_t1l + (size_t)img * IMG;
                                    bH = g_Ch;  bL = g_Cl; }

    const uint32_t smem_base = smem_u32(smem);

    auto issue = [&](int k0, int b) {
        uint32_t base = smem_base + b * BUF_BYTES;
#pragma unroll
        for (int u = 0; u < 2; u++) {
            int idx = tid + 256 * u;
            int m = idx >> 2, k8 = (idx & 3) * 8;
            size_t goff = (size_t)(m0 + m) * NDIM + k0 + k8;
            uint32_t soff = (uint32_t)(m * SA + k8) * 2;
            cpa16(base + soff, aH + goff);
            cpa16(base + A_BYTES + soff, aL + goff);
        }
#pragma unroll
        for (int u = 0; u < 2; u++) {
            int idx = tid + 256 * u;
            int k = idx >> 4, n8 = (idx & 15) * 8;
            size_t goff = (size_t)(k0 + k) * NDIM + n0 + n8;
            uint32_t soff = (uint32_t)(k * SBN + n8) * 2;
            cpa16(base + 2 * A_BYTES + soff, bH + goff);
            cpa16(base + 2 * A_BYTES + B_BYTES + soff, bL + goff);
        }
    };

    float d[2][8][4];
#pragma unroll
    for (int i = 0; i < 2; i++)
#pragma unroll
        for (int j = 0; j < 8; j++)
#pragma unroll
            for (int q = 0; q < 4; q++) d[i][j][q] = 0.0f;

    issue(0, 0);
    asm volatile("cp.async.commit_group;" ::: "memory");
    issue(BK, 1);   // always in-bounds; unused when niter==1
    asm volatile("cp.async.commit_group;" ::: "memory");

    for (int it = 0; it < niter; it++) {
        asm volatile("cp.async.wait_group 1;" ::: "memory");
        __syncthreads();

        const int b = it & 1;
        const uint32_t ahB = smem_base + b * BUF_BYTES;
        const uint32_t alB = ahB + A_BYTES;
        const uint32_t bhB = ahB + 2 * A_BYTES;
        const uint32_t blB = bhB + B_BYTES;

#pragma unroll
        for (int kk = 0; kk < BK; kk += 16) {
            uint32_t fAh[2][4], fAl[2][4];
#pragma unroll
            for (int mt = 0; mt < 2; mt++) {
                int row = wm * 32 + mt * 16 + (lane & 7) + ((lane >> 3) & 1) * 8;
                int col = kk + (lane >> 4) * 8;
                uint32_t off = (uint32_t)(row * SA + col) * 2;
                ldsm4(fAh[mt], ahB + off);
                ldsm4(fAl[mt], alB + off);
            }
#pragma unroll
            for (int nt2 = 0; nt2 < 4; nt2++) {
                int row = kk + (lane & 7) + ((lane >> 3) & 1) * 8;
                int col = wn * 64 + nt2 * 16 + (lane >> 4) * 8;
                uint32_t off = (uint32_t)(row * SBN + col) * 2;
                uint32_t rh[4], rl[4];
                ldsm4t(rh, bhB + off);
                ldsm4t(rl, blB + off);
#pragma unroll
                for (int mt = 0; mt < 2; mt++) {
                    mma16816(d[mt][nt2 * 2 + 0], fAh[mt], &rh[0]);
                    mma16816(d[mt][nt2 * 2 + 0], fAh[mt], &rl[0]);
                    mma16816(d[mt][nt2 * 2 + 0], fAl[mt], &rh[0]);
                    mma16816(d[mt][nt2 * 2 + 1], fAh[mt], &rh[2]);
                    mma16816(d[mt][nt2 * 2 + 1], fAh[mt], &rl[2]);
                    mma16816(d[mt][nt2 * 2 + 1], fAl[mt], &rh[2]);
                }
            }
        }
        __syncthreads();
        if (it + 2 < niter) issue((it + 2) * BK, b);
        asm volatile("cp.async.commit_group;" ::: "memory");
    }

    // ---- epilogue ----
    const int g = lane >> 2, q = lane & 3;

    if constexpr (MODE == 1) {
        // mask = 0.999 * fadeT (threshold-exact; 0.001 floor handled in MODE 3)
        const float PI_N = 0.01227184630308513f;  // pi/256
        float tb = tarr[img / 3];
        float sig = expf(fmaf(tb, 3.6888794541139363f, -0.6931471805599453f));
        float tau = 0.5f * sig * sig;
        float rf[2][2], cf[8][2];
#pragma unroll
        for (int mt = 0; mt < 2; mt++) {
            int r0 = m0 + wm * 32 + mt * 16 + g;
            float f0 = (float)r0 * PI_N, f1 = (float)(r0 + 8) * PI_N;
            rf[mt][0] = expf(-f0 * f0 * tau);
            rf[mt][1] = expf(-f1 * f1 * tau);
        }
#pragma unroll
        for (int nt = 0; nt < 8; nt++) {
            int c0 = n0 + wn * 64 + nt * 8 + q * 2;
            float f0 = (float)c0 * PI_N, f1 = (float)(c0 + 1) * PI_N;
            cf[nt][0] = expf(-f0 * f0 * tau);
            cf[nt][1] = expf(-f1 * f1 * tau);
        }
        __nv_bfloat16* oH = g_t2h + (size_t)img * IMG;
        __nv_bfloat16* oL = g_t2l + (size_t)img * IMG;
#pragma unroll
        for (int mt = 0; mt < 2; mt++)
#pragma unroll
            for (int nt = 0; nt < 8; nt++) {
                int r0 = m0 + wm * 32 + mt * 16 + g;
                int c0 = n0 + wn * 64 + nt * 8 + q * 2;
#pragma unroll
                for (int rh = 0; rh < 2; rh++) {
                    float fa0 = rf[mt][rh] * cf[nt][0];
                    float fa1 = rf[mt][rh] * cf[nt][1];
                    if (fa0 < 0.01f) fa0 = 0.0f;
                    if (fa1 < 0.01f) fa1 = 0.0f;
                    float v0 = d[mt][nt][rh * 2 + 0] * (0.999f * fa0);
                    float v1 = d[mt][nt][rh * 2 + 1] * (0.999f * fa1);
                    split_store_pair(oH, oL, (size_t)(r0 + rh * 8) * NDIM + c0, v0, v1);
                }
            }
    } else if constexpr (MODE == 3) {
        float* outImg = gout + (size_t)img * IMG;
        const float* xim = xin + (size_t)img * IMG;
#pragma unroll
        for (int mt = 0; mt < 2; mt++)
#pragma unroll
            for (int nt = 0; nt < 8; nt++) {
                int r0 = m0 + wm * 32 + mt * 16 + g;
                int c0 = n0 + wn * 64 + nt * 8 + q * 2;
#pragma unroll
                for (int rh = 0; rh < 2; rh++) {
                    size_t off = (size_t)(r0 + rh * 8) * NDIM + c0;
                    float2 xv = *reinterpret_cast<const float2*>(&xim[off]);
                    float2 o = make_float2(fmaf(0.001f, xv.x, d[mt][nt][rh * 2 + 0]),
                                           fmaf(0.001f, xv.y, d[mt][nt][rh * 2 + 1]));
                    *reinterpret_cast<float2*>(&outImg[off]) = o;
                }
            }
    } else {
        __nv_bfloat16* oH = g_t1h + (size_t)img * IMG;
        __nv_bfloat16* oL = g_t1l + (size_t)img * IMG;
#pragma unroll
        for (int mt = 0; mt < 2; mt++)
#pragma unroll
            for (int nt = 0; nt < 8; nt++) {
                int r0 = m0 + wm * 32 + mt * 16 + g;
                int c0 = n0 + wn * 64 + nt * 8 + q * 2;
#pragma unroll
                for (int rh = 0; rh < 2; rh++) {
                    split_store_pair(oH, oL, (size_t)(r0 + rh * 8) * NDIM + c0,
                                     d[mt][nt][rh * 2 + 0], d[mt][nt][rh * 2 + 1]);
                }
            }
    }
}

extern "C" void kernel_launch(void* const* d_in, const int* in_sizes, int n_in,
                              void* d_out, int out_size) {
    const float* x = (const float*)d_in[0];   // (128,3,256,256) fp32
    const float* t = (const float*)d_in[1];   // (128,) fp32
    float* out = (float*)d_out;               // (128,3,256,256) fp32

    cudaFuncSetAttribute(dct_mma<0>, cudaFuncAttributeMaxDynamicSharedMemorySize, SMEM_BYTES);
    cudaFuncSetAttribute(dct_mma<1>, cudaFuncAttributeMaxDynamicSharedMemorySize, SMEM_BYTES);
    cudaFuncSetAttribute(dct_mma<2>, cudaFuncAttributeMaxDynamicSharedMemorySize, SMEM_BYTES);
    cudaFuncSetAttribute(dct_mma<3>, cudaFuncAttributeMaxDynamicSharedMemorySize, SMEM_BYTES);

    init_C_kernel<<<(IMG + 255) / 256, 256>>>();
    split_x_kernel<<<(NIMG * IMG) / (256 * 4), 256>>>(x);

    dim3 blk(256, 1, 1);
    dim3 grd(NDIM / BN, NDIM / BM, NIMG);  // (2, 2, 384)
    dct_mma<0><<<grd, blk, SMEM_BYTES>>>(x, nullptr, t);
    dct_mma<1><<<grd, blk, SMEM_BYTES>>>(x, nullptr, t);
    dct_mma<2><<<grd, blk, SMEM_BYTES>>>(x, nullptr, t);
    dct_mma<3><<<grd, blk, SMEM_BYTES>>>(x, out, t);
}

// round 12
// speedup vs baseline: 3.8516x; 1.0034x over previous
#include <cuda_runtime.h>
#include <cuda_bf16.h>
#include <cstdint>
#include <math.h>

#define NDIM 256
#define IMG (NDIM * NDIM)
#define NIMG (128 * 3)
#define BM 128
#define BN 128
#define BK 32
#define SA 40    // A smem row stride (bf16): 80B = 5*16B odd -> conflict-free ldmatrix
#define SBN 136  // B smem row stride (bf16): 272B = 17*16B odd -> conflict-free

#define A_BYTES (BM * SA * 2)                  // 10240
#define B_BYTES (BK * SBN * 2)                 // 8704
#define BUF_BYTES (2 * A_BYTES + 2 * B_BYTES)  // 37888
#define SMEM_BYTES (2 * BUF_BYTES)             // 75776

// ---- device globals (no allocation allowed) ----
__device__ __nv_bfloat16 g_Ch[IMG], g_Cl[IMG];
__device__ __nv_bfloat16 g_CTh[IMG], g_CTl[IMG];
__device__ __nv_bfloat16 g_t1h[NIMG * IMG], g_t1l[NIMG * IMG];
__device__ __nv_bfloat16 g_t2h[NIMG * IMG], g_t2l[NIMG * IMG];

// DCT-II orthonormal matrix, pre-split into bf16 hi/lo, plus transpose.
__global__ void init_C_kernel() {
    int idx = blockIdx.x * blockDim.x + threadIdx.x;
    if (idx >= IMG) return;
    int k = idx >> 8, n = idx & 255;
    double v = cos(M_PI * ((double)n + 0.5) * (double)k / (double)NDIM);
    double s = (k == 0) ? sqrt(1.0 / NDIM) : sqrt(2.0 / NDIM);
    float f = (float)(v * s);
    __nv_bfloat16 h = __float2bfloat16_rn(f);
    __nv_bfloat16 l = __float2bfloat16_rn(f - __bfloat162float(h));
    g_Ch[k * NDIM + n] = h;
    g_Cl[k * NDIM + n] = l;
    g_CTh[n * NDIM + k] = h;
    g_CTl[n * NDIM + k] = l;
}

// Pre-split X (fp32) into bf16 hi/lo pairs stored in g_t2 (free at stage 0).
__global__ void split_x_kernel(const float* __restrict__ x) {
    size_t i = ((size_t)blockIdx.x * 256 + threadIdx.x) * 4;
    float4 v = *reinterpret_cast<const float4*>(x + i);
    __nv_bfloat162 h0, h1, l0, l1;
    h0.x = __float2bfloat16_rn(v.x); h0.y = __float2bfloat16_rn(v.y);
    h1.x = __float2bfloat16_rn(v.z); h1.y = __float2bfloat16_rn(v.w);
    l0.x = __float2bfloat16_rn(v.x - __bfloat162float(h0.x));
    l0.y = __float2bfloat16_rn(v.y - __bfloat162float(h0.y));
    l1.x = __float2bfloat16_rn(v.z - __bfloat162float(h1.x));
    l1.y = __float2bfloat16_rn(v.w - __bfloat162float(h1.y));
    *reinterpret_cast<__nv_bfloat162*>(g_t2h + i) = h0;
    *reinterpret_cast<__nv_bfloat162*>(g_t2h + i + 2) = h1;
    *reinterpret_cast<__nv_bfloat162*>(g_t2l + i) = l0;
    *reinterpret_cast<__nv_bfloat162*>(g_t2l + i + 2) = l1;
}

__device__ __forceinline__ uint32_t smem_u32(const void* p) {
    return (uint32_t)__cvta_generic_to_shared(p);
}
__device__ __forceinline__ void cpa16(uint32_t s, const void* g) {
    asm volatile("cp.async.cg.shared.global [%0], [%1], 16;" :: "r"(s), "l"(g));
}
__device__ __forceinline__ void ldsm4(uint32_t* r, uint32_t addr) {
    asm volatile("ldmatrix.sync.aligned.m8n8.x4.shared.b16 {%0,%1,%2,%3}, [%4];"
                 : "=r"(r[0]), "=r"(r[1]), "=r"(r[2]), "=r"(r[3]) : "r"(addr));
}
__device__ __forceinline__ void ldsm4t(uint32_t* r, uint32_t addr) {
    asm volatile("ldmatrix.sync.aligned.m8n8.x4.trans.shared.b16 {%0,%1,%2,%3}, [%4];"
                 : "=r"(r[0]), "=r"(r[1]), "=r"(r[2]), "=r"(r[3]) : "r"(addr));
}
__device__ __forceinline__ void mma16816(float* d, const uint32_t* a, const uint32_t* b) {
    asm volatile(
        "mma.sync.aligned.m16n8k16.row.col.f32.bf16.bf16.f32 "
        "{%0,%1,%2,%3}, {%4,%5,%6,%7}, {%8,%9}, {%0,%1,%2,%3};"
        : "+f"(d[0]), "+f"(d[1]), "+f"(d[2]), "+f"(d[3])
        : "r"(a[0]), "r"(a[1]), "r"(a[2]), "r"(a[3]), "r"(b[0]), "r"(b[1]));
}
__device__ __forceinline__ void split_store_pair(__nv_bfloat16* baseH, __nv_bfloat16* baseL,
                                                 size_t off, float v0, float v1) {
    __nv_bfloat16 h0 = __float2bfloat16_rn(v0);
    __nv_bfloat16 h1 = __float2bfloat16_rn(v1);
    __nv_bfloat162 hp; hp.x = h0; hp.y = h1;
    __nv_bfloat162 lp;
    lp.x = __float2bfloat16_rn(v0 - __bfloat162float(h0));
    lp.y = __float2bfloat16_rn(v1 - __bfloat162float(h1));
    *reinterpret_cast<__nv_bfloat162*>(baseH + off) = hp;
    *reinterpret_cast<__nv_bfloat162*>(baseL + off) = lp;
}

// Frequency cutoff: entries (k,n) with fade >= 0.01 require k,n < Km.
// Km = (256/pi)*sqrt(2 ln 100)/sigma = 247.31/sigma (+2 conservative margin).
// Identical fp sequence in all stages -> identical Km everywhere.
__device__ __forceinline__ int compute_Km(float tb) {
    float sig = expf(fmaf(tb, 3.6888794541139363f, -0.6931471805599453f));
    int km = (int)(247.32f / sig) + 2;
    return km > NDIM ? NDIM : km;
}

// Batched Out = A*B per image (256^3), bf16 hi/lo 3-term split, cp.async pipeline.
// Exact frequency sparsity: out = 0.001*X + 0.999*C^T(fadeT . dct)C, fadeT zero
// outside [0,Km)^2 -> tile skips + truncated K-loops (all exact).
// MODE 0: T1 = C  * X     A: g_C      B: g_t2 (X presplit) -> g_t1  [rows < Km]
// MODE 1: Y  = T1 * C^T   A: g_t1     B: g_CT              -> g_t2  [tiles < Km; mask 0.999*fadeT]
// MODE 2: T2 = C^T* Y     A: g_CT    B: g_t2              -> g_t1  [cols < Km; K < Km32]
// MODE 3: out= T2 * C     A: g_t1     B: g_C               -> out   [K < Km32; +0.001*X]
template <int MODE>
__global__ void __launch_bounds__(256, 2) dct_mma(const float* __restrict__ xin,
                                                  float* __restrict__ gout,
                                                  const float* __restrict__ tarr) {
    extern __shared__ __align__(16) unsigned char smem[];

    const int img = blockIdx.z;
    const int m0 = blockIdx.y * BM;
    const int n0 = blockIdx.x * BN;

    const int Km = compute_Km(tarr[img / 3]);
    if constexpr (MODE == 0) { if (m0 >= Km) return; }
    if constexpr (MODE == 1) { if (m0 >= Km || n0 >= Km) return; }
    if constexpr (MODE == 2) { if (n0 >= Km) return; }
    int kend;
    if constexpr (MODE >= 2) {
        int km32 = (Km + 31) & ~31;
        kend = km32 > NDIM ? NDIM : km32;
    } else {
        kend = NDIM;
    }
    const int niter = kend / BK;

    const int tid = threadIdx.x;
    const int wid = tid >> 5;
    const int lane = tid & 31;
    const int wm = wid & 3;   // 4 warps along m (32 rows each)
    const int wn = wid >> 2;  // 2 warps along n (64 cols each)

    const __nv_bfloat16 *aH, *aL, *bH, *bL;
    if constexpr (MODE == 0)      { aH = g_Ch;  aL = g_Cl;
                                    bH = g_t2h + (size_t)img * IMG; bL = g_t2l + (size_t)img * IMG; }
    else if constexpr (MODE == 1) { aH = g_t1h + (size_t)img * IMG; aL = g_t1l + (size_t)img * IMG;
                                    bH = g_CTh; bL = g_CTl; }
    else if constexpr (MODE == 2) { aH = g_CTh; aL = g_CTl;
                                    bH = g_t2h + (size_t)img * IMG; bL = g_t2l + (size_t)img * IMG; }
    else                          { aH = g_t1h + (size_t)img * IMG; aL = g_t1l + (size_t)img * IMG;
                                    bH = g_Ch;  bL = g_Cl; }

    const uint32_t smem_base = smem_u32(smem);

    auto issue = [&](int k0, int b) {
        uint32_t base = smem_base + b * BUF_BYTES;
#pragma unroll
        for (int u = 0; u < 2; u++) {
            int idx = tid + 256 * u;
            int m = idx >> 2, k8 = (idx & 3) * 8;
            size_t goff = (size_t)(m0 + m) * NDIM + k0 + k8;
            uint32_t soff = (uint32_t)(m * SA + k8) * 2;
            cpa16(base + soff, aH + goff);
            cpa16(base + A_BYTES + soff, aL + goff);
        }
#pragma unroll
        for (int u = 0; u < 2; u++) {
            int idx = tid + 256 * u;
            int k = idx >> 4, n8 = (idx & 15) * 8;
            size_t goff = (size_t)(k0 + k) * NDIM + n0 + n8;
            uint32_t soff = (uint32_t)(k * SBN + n8) * 2;
            cpa16(base + 2 * A_BYTES + soff, bH + goff);
            cpa16(base + 2 * A_BYTES + B_BYTES + soff, bL + goff);
        }
    };

    float d[2][8][4];
#pragma unroll
    for (int i = 0; i < 2; i++)
#pragma unroll
        for (int j = 0; j < 8; j++)
#pragma unroll
            for (int q = 0; q < 4; q++) d[i][j][q] = 0.0f;

    issue(0, 0);
    asm volatile("cp.async.commit_group;" ::: "memory");
    issue(BK, 1);   // always in-bounds; unused when niter==1
    asm volatile("cp.async.commit_group;" ::: "memory");

    for (int it = 0; it < niter; it++) {
        asm volatile("cp.async.wait_group 1;" ::: "memory");
        __syncthreads();

        const int b = it & 1;
        const uint32_t ahB = smem_base + b * BUF_BYTES;
        const uint32_t alB = ahB + A_BYTES;
        const uint32_t bhB = ahB + 2 * A_BYTES;
        const uint32_t blB = bhB + B_BYTES;

#pragma unroll
        for (int kk = 0; kk < BK; kk += 16) {
            uint32_t fAh[2][4], fAl[2][4];
#pragma unroll
            for (int mt = 0; mt < 2; mt++) {
                int row = wm * 32 + mt * 16 + (lane & 7) + ((lane >> 3) & 1) * 8;
                int col = kk + (lane >> 4) * 8;
                uint32_t off = (uint32_t)(row * SA + col) * 2;
                ldsm4(fAh[mt], ahB + off);
                ldsm4(fAl[mt], alB + off);
            }
#pragma unroll
            for (int nt2 = 0; nt2 < 4; nt2++) {
                int row = kk + (lane & 7) + ((lane >> 3) & 1) * 8;
                int col = wn * 64 + nt2 * 16 + (lane >> 4) * 8;
                uint32_t off = (uint32_t)(row * SBN + col) * 2;
                uint32_t rh[4], rl[4];
                ldsm4t(rh, bhB + off);
                ldsm4t(rl, blB + off);
#pragma unroll
                for (int mt = 0; mt < 2; mt++) {
                    mma16816(d[mt][nt2 * 2 + 0], fAh[mt], &rh[0]);
                    mma16816(d[mt][nt2 * 2 + 0], fAh[mt], &rl[0]);
                    mma16816(d[mt][nt2 * 2 + 0], fAl[mt], &rh[0]);
                    mma16816(d[mt][nt2 * 2 + 1], fAh[mt], &rh[2]);
                    mma16816(d[mt][nt2 * 2 + 1], fAh[mt], &rl[2]);
                    mma16816(d[mt][nt2 * 2 + 1], fAl[mt], &rh[2]);
                }
            }
        }
        __syncthreads();
        if (it + 2 < niter) issue((it + 2) * BK, b);
        asm volatile("cp.async.commit_group;" ::: "memory");
    }

    // ---- epilogue ----
    const int g = lane >> 2, q = lane & 3;

    if constexpr (MODE == 1) {
        // mask = 0.999 * fadeT (threshold-exact; 0.001 floor handled in MODE 3)
        const float PI_N = 0.01227184630308513f;  // pi/256
        float tb = tarr[img / 3];
        float sig = expf(fmaf(tb, 3.6888794541139363f, -0.6931471805599453f));
        float tau = 0.5f * sig * sig;
        float rf[2][2], cf[8][2];
#pragma unroll
        for (int mt = 0; mt < 2; mt++) {
            int r0 = m0 + wm * 32 + mt * 16 + g;
            float f0 = (float)r0 * PI_N, f1 = (float)(r0 + 8) * PI_N;
            rf[mt][0] = expf(-f0 * f0 * tau);
            rf[mt][1] = expf(-f1 * f1 * tau);
        }
#pragma unroll
        for (int nt = 0; nt < 8; nt++) {
            int c0 = n0 + wn * 64 + nt * 8 + q * 2;
            float f0 = (float)c0 * PI_N, f1 = (float)(c0 + 1) * PI_N;
            cf[nt][0] = expf(-f0 * f0 * tau);
            cf[nt][1] = expf(-f1 * f1 * tau);
        }
        __nv_bfloat16* oH = g_t2h + (size_t)img * IMG;
        __nv_bfloat16* oL = g_t2l + (size_t)img * IMG;
#pragma unroll
        for (int mt = 0; mt < 2; mt++)
#pragma unroll
            for (int nt = 0; nt < 8; nt++) {
                int r0 = m0 + wm * 32 + mt * 16 + g;
                int c0 = n0 + wn * 64 + nt * 8 + q * 2;
#pragma unroll
                for (int rh = 0; rh < 2; rh++) {
                    float fa0 = rf[mt][rh] * cf[nt][0];
                    float fa1 = rf[mt][rh] * cf[nt][1];
                    if (fa0 < 0.01f) fa0 = 0.0f;
                    if (fa1 < 0.01f) fa1 = 0.0f;
                    float v0 = d[mt][nt][rh * 2 + 0] * (0.999f * fa0);
                    float v1 = d[mt][nt][rh * 2 + 1] * (0.999f * fa1);
                    split_store_pair(oH, oL, (size_t)(r0 + rh * 8) * NDIM + c0, v0, v1);
                }
            }
    } else if constexpr (MODE == 3) {
        float* outImg = gout + (size_t)img * IMG;
        const float* xim = xin + (size_t)img * IMG;
#pragma unroll
        for (int mt = 0; mt < 2; mt++)
#pragma unroll
            for (int nt = 0; nt < 8; nt++) {
                int r0 = m0 + wm * 32 + mt * 16 + g;
                int c0 = n0 + wn * 64 + nt * 8 + q * 2;
#pragma unroll
                for (int rh = 0; rh < 2; rh++) {
                    size_t off = (size_t)(r0 + rh * 8) * NDIM + c0;
                    float2 xv = *reinterpret_cast<const float2*>(&xim[off]);
                    float2 o = make_float2(fmaf(0.001f, xv.x, d[mt][nt][rh * 2 + 0]),
                                           fmaf(0.001f, xv.y, d[mt][nt][rh * 2 + 1]));
                    *reinterpret_cast<float2*>(&outImg[off]) = o;
                }
            }
    } else {
        __nv_bfloat16* oH = g_t1h + (size_t)img * IMG;
        __nv_bfloat16* oL = g_t1l + (size_t)img * IMG;
#pragma unroll
        for (int mt = 0; mt < 2; mt++)
#pragma unroll
            for (int nt = 0; nt < 8; nt++) {
                int r0 = m0 + wm * 32 + mt * 16 + g;
                int c0 = n0 + wn * 64 + nt * 8 + q * 2;
#pragma unroll
                for (int rh = 0; rh < 2; rh++) {
                    split_store_pair(oH, oL, (size_t)(r0 + rh * 8) * NDIM + c0,
                                     d[mt][nt][rh * 2 + 0], d[mt][nt][rh * 2 + 1]);
                }
            }
    }
}

extern "C" void kernel_launch(void* const* d_in, const int* in_sizes, int n_in,
                              void* d_out, int out_size) {
    const float* x = (const float*)d_in[0];   // (128,3,256,256) fp32
    const float* t = (const float*)d_in[1];   // (128,) fp32
    float* out = (float*)d_out;               // (128,3,256,256) fp32

    cudaFuncSetAttribute(dct_mma<0>, cudaFuncAttributeMaxDynamicSharedMemorySize, SMEM_BYTES);
    cudaFuncSetAttribute(dct_mma<1>, cudaFuncAttributeMaxDynamicSharedMemorySize, SMEM_BYTES);
    cudaFuncSetAttribute(dct_mma<2>, cudaFuncAttributeMaxDynamicSharedMemorySize, SMEM_BYTES);
    cudaFuncSetAttribute(dct_mma<3>, cudaFuncAttributeMaxDynamicSharedMemorySize, SMEM_BYTES);

    init_C_kernel<<<(IMG + 255) / 256, 256>>>();
    split_x_kernel<<<(NIMG * IMG) / (256 * 4), 256>>>(x);

    dim3 blk(256, 1, 1);
    dim3 grd(NDIM / BN, NDIM / BM, NIMG);  // (2, 2, 384)
    dct_mma<0><<<grd, blk, SMEM_BYTES>>>(x, nullptr, t);
    dct_mma<1><<<grd, blk, SMEM_BYTES>>>(x, nullptr, t);
    dct_mma<2><<<grd, blk, SMEM_BYTES>>>(x, nullptr, t);
    dct_mma<3><<<grd, blk, SMEM_BYTES>>>(x, out, t);
}